// round 1
// baseline (speedup 1.0000x reference)
#include <cuda_runtime.h>
#include <math.h>

#define NB 128
#define NT 30
#define NG 13
#define NC 16
#define NCELLS 169
#define NANCH 507            // 169*3
#define ROWLEN 21
#define ROWS_FULL 10647

__device__ __forceinline__ float warp_sum(float v) {
    #pragma unroll
    for (int o = 16; o > 0; o >>= 1) v += __shfl_down_sync(0xffffffffu, v, o);
    return v;
}

__global__ void zero_kernel(float* out) {
    if (threadIdx.x == 0) out[0] = 0.0f;
}

__global__ void __launch_bounds__(256) region_loss_kernel(
    const float* __restrict__ outp,   // (128, 10647, 21)
    const float* __restrict__ tgt,    // (128, 30, 5)
    float* __restrict__ loss)
{
    const int b = blockIdx.x;
    const int tid = threadIdx.x;

    __shared__ int   s_cell2t[NCELLS];
    __shared__ float s_iou[NT][3];
    __shared__ int   s_maxa[NT];
    __shared__ float s_maxiou[NT];
    __shared__ float s_locx[NT], s_locy[NT], s_tw[NT], s_th[NT];
    __shared__ int   s_cls[NT];
    __shared__ float s_warp[8];

    for (int i = tid; i < NCELLS; i += blockDim.x) s_cell2t[i] = -1;
    __syncthreads();

    if (tid < NT) {
        const float* tg = tgt + ((size_t)b * NT + tid) * 5;
        const float x1 = tg[0], y1 = tg[1], x2 = tg[2], y2 = tg[3];
        const float lx = (x1 + x2) * 0.5f;
        const float ly = (y1 + y2) * 0.5f;
        const int idx = (int)floorf(ly / 32.0f) * NG + (int)floorf(lx / 32.0f);

        float best_iou = -INFINITY;
        int best_a = 0;
        #pragma unroll
        for (int a = 0; a < 3; a++) {
            const float* p = outp + ((size_t)b * ROWS_FULL + (size_t)idx * 3 + a) * ROWLEN;
            const float px = p[0], py = p[1], pw = p[2], ph = p[3];
            const float bx1 = px - pw * 0.5f, by1 = py - ph * 0.5f;
            const float bx2 = px + pw * 0.5f, by2 = py + ph * 0.5f;
            const float ix1 = fmaxf(bx1, x1), iy1 = fmaxf(by1, y1);
            const float ix2 = fminf(bx2, x2), iy2 = fminf(by2, y2);
            const float inter = fmaxf(ix2 - ix1, 0.0f) * fmaxf(iy2 - iy1, 0.0f);
            const float a1 = (bx2 - bx1) * (by2 - by1);
            const float a2 = (x2 - x1) * (y2 - y1);
            const float iou = inter / (a1 + a2 - inter + 1e-16f);
            s_iou[tid][a] = iou;
            if (iou > best_iou) { best_iou = iou; best_a = a; }
        }
        s_maxa[tid]   = best_a;
        s_maxiou[tid] = best_iou;
        s_locx[tid]   = lx;
        s_locy[tid]   = ly;
        s_tw[tid]     = x2 - x1;
        s_th[tid]     = y2 - y1;
        s_cls[tid]    = (int)tg[4];
        s_cell2t[idx] = tid;
    }
    __syncthreads();

    const float SQRT5 = 2.2360679774997896f;
    const float INVW  = 1.0f / 416.0f;

    float acc = 0.0f;
    for (int j = tid; j < NANCH; j += blockDim.x) {
        const int cell = j / 3;
        const int a    = j - cell * 3;
        const float* p = outp + ((size_t)b * ROWS_FULL + j) * ROWLEN;
        const float conf = p[4];
        const int t = s_cell2t[cell];
        if (t < 0) {
            acc += conf * conf;
        } else {
            float cm, tc = 0.0f;
            if (a == s_maxa[t]) {
                cm = SQRT5;
                tc = s_maxiou[t];
                // class loss (argmax anchor only)
                const int c0 = s_cls[t];
                #pragma unroll
                for (int c = 0; c < NC; c++) {
                    const float d = p[5 + c] - (c == c0 ? 1.0f : 0.0f);
                    acc += d * d;
                }
                // coord loss
                const float tw = s_tw[t], th = s_th[t];
                const float wgt = 2.0f - (tw * INVW) * (th * INVW);
                const float k = wgt * INVW;
                const float dx = (p[0] - s_locx[t]) * k;
                const float dy = (p[1] - s_locy[t]) * k;
                const float dw = (p[2] - tw) * k;
                const float dh = (p[3] - th) * k;
                acc += dx * dx + dy * dy + dw * dw + dh * dh;
            } else {
                cm = (s_iou[t][a] > 0.5f) ? 0.0f : 1.0f;
            }
            const float d = (conf - tc) * cm;
            acc += d * d;
        }
    }
    acc *= 0.5f;

    // block reduction
    acc = warp_sum(acc);
    const int lane = tid & 31, wid = tid >> 5;
    if (lane == 0) s_warp[wid] = acc;
    __syncthreads();
    if (wid == 0) {
        float v = (lane < 8) ? s_warp[lane] : 0.0f;
        v = warp_sum(v);
        if (lane == 0) atomicAdd(loss, v);
    }
}

extern "C" void kernel_launch(void* const* d_in, const int* in_sizes, int n_in,
                              void* d_out, int out_size) {
    const float* outp = (const float*)d_in[0];
    const float* tgt  = (const float*)d_in[1];
    float* loss = (float*)d_out;
    zero_kernel<<<1, 32>>>(loss);
    region_loss_kernel<<<NB, 256>>>(outp, tgt, loss);
}